// round 2
// baseline (speedup 1.0000x reference)
#include <cuda_runtime.h>

// Exact integer reformulation of the PUMA crossbar MVM conv (validated R1):
//   out = RNE_clip( conv_int(xi16, dw) / 4096 ) / 4096
// where xi16 = sext16(rint(x*4096)), dw = clamp(rint(w*4096), +/-65535).
//
// R2 structure: 512 blocks x 128 threads, 2 Cout per thread, single SMEM
// staging phase with one barrier. SMEM 43.8KB static -> ~3.5 blocks/SM,
// ~14 warps/SM vs 8 before; 1 barrier vs 8.

namespace {
constexpr int CIN = 64, H = 16, W = 16, COUT = 128;
constexpr int CO_CHUNK = 16;     // Cout per block
constexpr int THREADS  = 128;    // 16 ow x 8 cog(2 Cout)
constexpr int L        = CIN * 9;  // 576 taps
}

__global__ __launch_bounds__(THREADS, 8)
void conv_mvm_kernel(const float* __restrict__ x,
                     const float* __restrict__ w,
                     float* __restrict__ out)
{
    __shared__ int   sw[L * CO_CHUNK];   // 36864 B : [tap l][co_local]
    __shared__ short sx[CIN * 3 * 18];   //  6912 B : [ci][row 0..2][col -1..16]

    const int bid    = blockIdx.x;          // 512 blocks
    const int coBase = (bid & 7) * CO_CHUNK;
    const int oh     = (bid >> 3) & 15;
    const int b      = bid >> 7;

    const int tid = threadIdx.x;
    const int ow  = tid & 15;
    const int cog = tid >> 4;               // 0..7 -> 2 consecutive Cout

    // ---- stage weights once: quantize on the fly, layout [l][co] ----
    #pragma unroll
    for (int it = 0; it < (L * CO_CHUNK) / THREADS; ++it) {
        int idx = it * THREADS + tid;
        int col = idx / L;                  // co_local: consecutive tid -> consecutive l (coalesced)
        int l   = idx - col * L;
        float wv = __ldg(&w[(coBase + col) * L + l]);
        int q = (int)rintf(wv * 4096.0f);   // == wpos - wneg exactly
        q = max(-65535, min(65535, q));
        sw[l * CO_CHUNK + col] = q;
    }

    // ---- stage inputs once: 64 ci x 3 rows x 18 cols, int16, zero-padded ----
    for (int idx = tid; idx < CIN * 3 * 18; idx += THREADS) {
        int col = idx % 18;
        int r   = (idx / 18) % 3;
        int ci  = idx / 54;
        int gr  = oh - 1 + r;
        int gc  = col - 1;
        short v = 0;
        if ((unsigned)gr < (unsigned)H && (unsigned)gc < (unsigned)W) {
            float xv = __ldg(&x[((b * CIN + ci) * H + gr) * W + gc]);
            int xi = (int)rintf(xv * 4096.0f);
            v = (short)xi;                  // 16-bit two's complement wrap (== ref bitstream)
        }
        sx[idx] = v;
    }
    __syncthreads();

    // ---- integer MAC mainloop: 576 taps x 2 Cout per thread ----
    int acc0 = 0, acc1 = 0;
    #pragma unroll 4
    for (int ci = 0; ci < CIN; ++ci) {
        const short* xp = &sx[ci * 54 + ow];
        const int*   wp = &sw[ci * 9 * CO_CHUNK + cog * 2];
        #pragma unroll
        for (int ki = 0; ki < 3; ++ki) {
            int x0 = xp[ki * 18 + 0];
            int x1 = xp[ki * 18 + 1];
            int x2 = xp[ki * 18 + 2];
            int2 w0 = *(const int2*)&wp[(ki * 3 + 0) * CO_CHUNK];
            int2 w1 = *(const int2*)&wp[(ki * 3 + 1) * CO_CHUNK];
            int2 w2 = *(const int2*)&wp[(ki * 3 + 2) * CO_CHUNK];
            acc0 += x0 * w0.x + x1 * w1.x + x2 * w2.x;
            acc1 += x0 * w0.y + x1 * w1.y + x2 * w2.y;
        }
    }

    // ---- epilogue: S/2^24 -> round-half-even to 1/4096 grid, clip int16 ----
    const int coOut = coBase + cog * 2;
    float* op = out + ((b * COUT + coOut) * H + oh) * W + ow;
    int accs[2] = {acc0, acc1};
    #pragma unroll
    for (int j = 0; j < 2; ++j) {
        int S    = accs[j];
        int base = S >> 12;                 // floor(S/4096)
        int rem  = S - (base << 12);        // 0..4095
        if (rem > 2048)       base += 1;
        else if (rem == 2048) base += (base & 1);   // ties to even
        base = max(-32768, min(32767, base));
        op[j * (H * W)] = (float)base * (1.0f / 4096.0f);
    }
}

extern "C" void kernel_launch(void* const* d_in, const int* in_sizes, int n_in,
                              void* d_out, int out_size) {
    const float* x = (const float*)d_in[0];
    const float* w = (const float*)d_in[1];
    // defensive: identify tensors by element count (x: 65536, w: 73728)
    if (n_in >= 2 && in_sizes[0] == 73728 && in_sizes[1] == 65536) {
        x = (const float*)d_in[1];
        w = (const float*)d_in[0];
    }
    conv_mvm_kernel<<<512, THREADS>>>(x, w, (float*)d_out);
}

// round 4
// speedup vs baseline: 1.8485x; 1.8485x over previous
#include <cuda_runtime.h>

// Exact integer reformulation of the PUMA crossbar MVM conv (validated R1/R2):
//   out = RNE_clip( conv_int(xi16, dw) / 4096 ) / 4096
//   xi16 = sext16(rint(x*4096)),  dw = clamp(rint(w*4096), +/-65535)
//
// R4 (= R3 with the weight-layout bug fixed): prep kernel pre-quantizes AND
// pre-transposes w into the SMEM tile layout [co_chunk][l][co_local], so the
// main kernel's weight staging is a pure linear int4 copy. x pre-quantized
// to int16. Main: 256 blocks x 128 threads, 4 Cout/thread via int4 LDS,
// 2 output rows per block, single barrier.

namespace {
constexpr int CIN = 64, H = 16, W = 16, COUT = 128;
constexpr int L = CIN * 9;            // 576
constexpr int CO_CHUNK = 16;
constexpr int THREADS = 128;          // ow16 x cog4 x ohsub2
}

__device__ int   g_w[COUT * L];        // quantized weights [co/16][l][co%16]
__device__ short g_x[4 * CIN * H * W]; // quantized inputs, same layout as x

__global__ void prep_kernel(const float* __restrict__ x,
                            const float* __restrict__ w)
{
    int i = blockIdx.x * blockDim.x + threadIdx.x;
    if (i < COUT * L) {
        int co = i / L;
        int l  = i - co * L;
        int q = (int)rintf(w[i] * 4096.0f);      // == wpos - wneg exactly
        q = max(-65535, min(65535, q));
        // tile layout: chunk-major, then l, then co within chunk
        g_w[(co / CO_CHUNK) * (L * CO_CHUNK) + l * CO_CHUNK + (co % CO_CHUNK)] = q;
    }
    if (i < 4 * CIN * H * W) {
        int xi = (int)rintf(x[i] * 4096.0f);
        g_x[i] = (short)xi;                      // 16-bit two's complement wrap
    }
}

__global__ __launch_bounds__(THREADS, 2)
void conv_mvm_kernel(float* __restrict__ out)
{
    __shared__ int   sw[L * CO_CHUNK];    // 36864 B : [l][co_local]
    __shared__ short sx[CIN * 4 * 18];    //  9216 B : [ci][row 0..3][col -1..16]

    const int bid    = blockIdx.x;          // 256 = 8co x 8ohp x 4b
    const int coChunk= bid & 7;
    const int ohp    = (bid >> 3) & 7;      // output-row pair
    const int b      = bid >> 6;

    const int tid   = threadIdx.x;
    const int ow    = tid & 15;
    const int cog   = (tid >> 4) & 3;       // group of 4 Cout
    const int ohsub = tid >> 6;

    // ---- stage weights: linear int4 copy, already in [l][co] tile layout ----
    {
        const int4* src = (const int4*)(g_w + coChunk * (L * CO_CHUNK));
        int4* dst = (int4*)sw;
        #pragma unroll
        for (int it = 0; it < (CO_CHUNK * L / 4) / THREADS; ++it)
            dst[it * THREADS + tid] = src[it * THREADS + tid];
    }

    // ---- stage inputs: 64 ci x 4 rows x 18 cols, pre-quantized, zero-pad ----
    #pragma unroll
    for (int it = 0; it < (CIN * 4 * 18) / THREADS; ++it) {
        int idx = it * THREADS + tid;
        int col = idx % 18;
        int r   = (idx / 18) & 3;
        int ci  = idx / 72;
        int gr  = ohp * 2 - 1 + r;
        int gc  = col - 1;
        short v = 0;
        if ((unsigned)gr < (unsigned)H && (unsigned)gc < (unsigned)W)
            v = g_x[((b * CIN + ci) * H + gr) * W + gc];
        sx[idx] = v;
    }
    __syncthreads();

    // ---- integer MAC mainloop: 576 taps x 4 Cout per thread ----
    int acc0 = 0, acc1 = 0, acc2 = 0, acc3 = 0;
    #pragma unroll 4
    for (int ci = 0; ci < CIN; ++ci) {
        const short* xp = &sx[ci * 72 + ohsub * 18 + ow];
        const int*   wp = &sw[ci * 9 * CO_CHUNK + cog * 4];
        #pragma unroll
        for (int ki = 0; ki < 3; ++ki) {
            int x0 = xp[ki * 18 + 0];
            int x1 = xp[ki * 18 + 1];
            int x2 = xp[ki * 18 + 2];
            int4 w0 = *(const int4*)&wp[(ki * 3 + 0) * CO_CHUNK];
            int4 w1 = *(const int4*)&wp[(ki * 3 + 1) * CO_CHUNK];
            int4 w2 = *(const int4*)&wp[(ki * 3 + 2) * CO_CHUNK];
            acc0 += x0 * w0.x + x1 * w1.x + x2 * w2.x;
            acc1 += x0 * w0.y + x1 * w1.y + x2 * w2.y;
            acc2 += x0 * w0.z + x1 * w1.z + x2 * w2.z;
            acc3 += x0 * w0.w + x1 * w1.w + x2 * w2.w;
        }
    }

    // ---- epilogue: S/2^24 -> RNE to 1/4096 grid, clip int16 ----
    const int oh    = ohp * 2 + ohsub;
    const int coOut = coChunk * CO_CHUNK + cog * 4;
    float* op = out + ((b * COUT + coOut) * H + oh) * W + ow;
    int accs[4] = {acc0, acc1, acc2, acc3};
    #pragma unroll
    for (int j = 0; j < 4; ++j) {
        int S    = accs[j];
        int base = S >> 12;                 // floor(S/4096)
        int rem  = S - (base << 12);        // 0..4095
        if (rem > 2048)       base += 1;
        else if (rem == 2048) base += (base & 1);   // ties to even
        base = max(-32768, min(32767, base));
        op[j * (H * W)] = (float)base * (1.0f / 4096.0f);
    }
}

extern "C" void kernel_launch(void* const* d_in, const int* in_sizes, int n_in,
                              void* d_out, int out_size) {
    const float* x = (const float*)d_in[0];
    const float* w = (const float*)d_in[1];
    // defensive: identify tensors by element count (x: 65536, w: 73728)
    if (n_in >= 2 && in_sizes[0] == 73728 && in_sizes[1] == 65536) {
        x = (const float*)d_in[1];
        w = (const float*)d_in[0];
    }
    prep_kernel<<<(COUT * L + 255) / 256, 256>>>(x, w);
    conv_mvm_kernel<<<256, THREADS>>>((float*)d_out);
}